// round 4
// baseline (speedup 1.0000x reference)
#include <cuda_runtime.h>
#include <stdint.h>

// ============================================================================
// VQ argmin via int8 dp4a (ALU pipe ~4x FFMA rate; tensor pipe unreachable on
// plain sm_103 target - tcgen05 is 'a'-gated, mma.sync is FFMA-emulated).
//   quant_cb: per-code scale sc, int8 qc (transposed packed), csq, ||ec||, ||cq||
//   quant_x : per-token scale sx, int8 qx (transposed packed), ||ex||, ||xq||
//   sweep   : approx dist = csq - 2*sx*sc*dp4a-dot; per-pair rigorous error
//             bound b; collect candidates with (approx-2b) <= min(approx+2b)
//   rescore : exact fp32 distance over candidates -> argmin (full scan if ovf)
//   gather  : out = codebook[idx]
// ============================================================================

#define NTOK   16384
#define DIM    256
#define KCODES 4096
#define HW     1024
#define MTILE  128          // tokens per CTA
#define CTILE  128          // codes per tile
#define TILES  (KCODES / CTILE)
#define D4     (DIM / 4)    // 64 packed dim-groups
#define CAP    64

// sweep smem offsets (bytes)
#define SM_A    0                   // 64*128*4 = 32768  qx[d4][token]
#define SM_B    32768               // 2*64*128*4 = 65536 qc tiles
#define SM_SX   98304               // 128 f32
#define SM_A0   98816               // 128 f32 ||xq||
#define SM_A1   99328               // 128 f32 ||ex||
#define SM_MIN  99840               // 128 u32
#define SM_CNT  100352              // 128 i32
#define SM_TOT  100864

__device__ float    g_csq[KCODES];
__device__ float    g_sc2[KCODES];          // 2*sc
__device__ float    g_e1[KCODES];           // ||ec||
__device__ float    g_n1[KCODES];           // ||cq||
__device__ unsigned g_qcT[D4 * KCODES];     // [d4][code]
__device__ unsigned g_qxT[D4 * NTOK];       // [d4][token]
__device__ float    g_sx[NTOK];
__device__ float    g_xa0[NTOK];            // ||xq||
__device__ float    g_xa1[NTOK];            // ||ex||
__device__ int      g_cnt[NTOK];
__device__ int      g_cand[(size_t)NTOK * CAP];
__device__ int      g_idx[NTOK];

// ---------------- helpers ----------------
__device__ __forceinline__ unsigned ford(float f) {   // order-preserving map
    unsigned u = __float_as_uint(f);
    return (u & 0x80000000u) ? ~u : (u | 0x80000000u);
}
__device__ __forceinline__ float ford_inv(unsigned u) {
    unsigned b = (u & 0x80000000u) ? (u ^ 0x80000000u) : ~u;
    return __uint_as_float(b);
}
__device__ __forceinline__ unsigned pack4(int q0, int q1, int q2, int q3) {
    return (unsigned)(q0 & 0xFF) | ((unsigned)(q1 & 0xFF) << 8) |
           ((unsigned)(q2 & 0xFF) << 16) | ((unsigned)q3 << 24);
}
#define CP16(d, s)  asm volatile("cp.async.cg.shared.global [%0], [%1], 16;" :: "r"(d), "l"(s))
#define CPCOMMIT()  asm volatile("cp.async.commit_group;" ::: "memory")
#define CPWAIT1()   asm volatile("cp.async.wait_group 1;" ::: "memory")
#define CPWAIT0()   asm volatile("cp.async.wait_group 0;" ::: "memory")
__device__ __forceinline__ uint32_t smem_u32(const void* p) {
    uint32_t a;
    asm("{ .reg .u64 t; cvta.to.shared.u64 t, %1; cvt.u32.u64 %0, t; }" : "=r"(a) : "l"(p));
    return a;
}

// ---------------- quantize codebook: 1 warp per code ----------------
__global__ __launch_bounds__(256) void quant_cb(const float* __restrict__ cb) {
    const int code = blockIdx.x * 8 + (threadIdx.x >> 5);
    const int lane = threadIdx.x & 31;
    const float* row = cb + (size_t)code * DIM;

    float v[8];
#pragma unroll
    for (int i = 0; i < 8; i++) v[i] = row[lane * 8 + i];

    float am = 0.f, sq = 0.f;
#pragma unroll
    for (int i = 0; i < 8; i++) { am = fmaxf(am, fabsf(v[i])); sq = fmaf(v[i], v[i], sq); }
#pragma unroll
    for (int o = 16; o > 0; o >>= 1) {
        am = fmaxf(am, __shfl_xor_sync(0xFFFFFFFFu, am, o));
        sq += __shfl_xor_sync(0xFFFFFFFFu, sq, o);
    }
    if (am < 1e-30f) am = 1e-30f;
    const float inv = 127.0f / am;
    const float sc  = am * (1.0f / 127.0f);

    int q[8];
    float e2 = 0.f, n2 = 0.f;
#pragma unroll
    for (int i = 0; i < 8; i++) {
        int qi = __float2int_rn(v[i] * inv);
        qi = max(-127, min(127, qi));
        q[i] = qi;
        float r = sc * (float)qi;
        float e = v[i] - r;
        e2 = fmaf(e, e, e2);
        n2 = fmaf(r, r, n2);
    }
#pragma unroll
    for (int o = 16; o > 0; o >>= 1) {
        e2 += __shfl_xor_sync(0xFFFFFFFFu, e2, o);
        n2 += __shfl_xor_sync(0xFFFFFFFFu, n2, o);
    }
    g_qcT[(lane * 2 + 0) * KCODES + code] = pack4(q[0], q[1], q[2], q[3]);
    g_qcT[(lane * 2 + 1) * KCODES + code] = pack4(q[4], q[5], q[6], q[7]);
    if (lane == 0) {
        g_csq[code] = sq;
        g_sc2[code] = 2.0f * sc;
        g_e1[code]  = sqrtf(e2);
        g_n1[code]  = sqrtf(n2);
    }
}

// ---------------- quantize x: 1 thread per token (lanes=adjacent tokens) ----
__global__ __launch_bounds__(128) void quant_x(const float* __restrict__ x) {
    const int n = blockIdx.x * 128 + threadIdx.x;
    const float* xr = x + (size_t)(n >> 10) * DIM * HW + (n & (HW - 1));

    float am = 0.f;
#pragma unroll 8
    for (int d = 0; d < DIM; d++) am = fmaxf(am, fabsf(xr[(size_t)d * HW]));
    if (am < 1e-30f) am = 1e-30f;
    const float inv = 127.0f / am;
    const float sc  = am * (1.0f / 127.0f);

    float e2 = 0.f, n2 = 0.f;
    for (int g = 0; g < D4; g++) {
        int q[4];
#pragma unroll
        for (int i = 0; i < 4; i++) {
            float v = xr[(size_t)(g * 4 + i) * HW];
            int qi = __float2int_rn(v * inv);
            qi = max(-127, min(127, qi));
            q[i] = qi;
            float r = sc * (float)qi;
            float e = v - r;
            e2 = fmaf(e, e, e2);
            n2 = fmaf(r, r, n2);
        }
        g_qxT[g * NTOK + n] = pack4(q[0], q[1], q[2], q[3]);
    }
    g_sx[n]  = sc;
    g_xa0[n] = sqrtf(n2);
    g_xa1[n] = sqrtf(e2);
}

// ---------------- main dp4a sweep ----------------
__global__ __launch_bounds__(256, 1) void sweep_kernel() {
    extern __shared__ char sm[];
    unsigned* A    = reinterpret_cast<unsigned*>(sm + SM_A);
    unsigned* B    = reinterpret_cast<unsigned*>(sm + SM_B);
    float*    sx_s = reinterpret_cast<float*>(sm + SM_SX);
    float*    a0_s = reinterpret_cast<float*>(sm + SM_A0);
    float*    a1_s = reinterpret_cast<float*>(sm + SM_A1);
    unsigned* minu = reinterpret_cast<unsigned*>(sm + SM_MIN);
    int*      cnts = reinterpret_cast<int*>(sm + SM_CNT);
    const uint32_t sb = smem_u32(sm);

    const int tid = threadIdx.x;
    const int ty  = tid >> 4;       // token group: tokens ty*8..+7
    const int tx  = tid & 15;       // code group:  codes  tx*8..+7
    const int n0  = blockIdx.x * MTILE;

    // A fill: qx [d4][128 tokens]
#pragma unroll
    for (int k = 0; k < 32; k++) {
        int i = tid + k * 256;                 // i < 8192
        int d4 = i >> 7, t = i & 127;
        A[d4 * 128 + t] = g_qxT[d4 * NTOK + n0 + t];
    }
    if (tid < MTILE) {
        sx_s[tid] = g_sx[n0 + tid];
        a0_s[tid] = g_xa0[n0 + tid];
        a1_s[tid] = g_xa1[n0 + tid];
        minu[tid] = 0xFFFFFFFFu;
        cnts[tid] = 0;
    }
    // B prologue: tile 0
    {
        const unsigned* src = g_qcT;
        for (int k = 0; k < 8; k++) {
            int q = tid + k * 256;             // q < 2048
            int d4 = q >> 5, seg = q & 31;
            CP16(sb + SM_B + (d4 * 128 + seg * 4) * 4,
                 src + d4 * KCODES + seg * 4);
        }
        CPCOMMIT();
    }
    __syncthreads();

    float sxv[8], a0v[8], a1v[8];
#pragma unroll
    for (int i = 0; i < 8; i++) {
        sxv[i] = sx_s[ty * 8 + i];
        a0v[i] = a0_s[ty * 8 + i];
        a1v[i] = a1_s[ty * 8 + i];
    }

    for (int ct = 0; ct < TILES; ct++) {
        // prefetch next tile
        if (ct + 1 < TILES) {
            const unsigned* src = g_qcT + (ct + 1) * CTILE;
            const uint32_t dst = sb + SM_B + ((ct + 1) & 1) * 32768;
            for (int k = 0; k < 8; k++) {
                int q = tid + k * 256;
                int d4 = q >> 5, seg = q & 31;
                CP16(dst + (d4 * 128 + seg * 4) * 4, src + d4 * KCODES + seg * 4);
            }
            CPCOMMIT();
            CPWAIT1();
        } else {
            CPWAIT0();
        }
        __syncthreads();

        // ---- dp4a mainloop: 8 tokens x 8 codes x 256 dims ----
        const unsigned* Ab = A + ty * 8;
        const unsigned* Bb = B + ((ct & 1) * 8192) + tx * 8;
        int acc[8][8];
#pragma unroll
        for (int i = 0; i < 8; i++)
#pragma unroll
            for (int j = 0; j < 8; j++) acc[i][j] = 0;

#pragma unroll 4
        for (int d4 = 0; d4 < D4; d4++) {
            uint4 al = *reinterpret_cast<const uint4*>(Ab + d4 * 128);
            uint4 ah = *reinterpret_cast<const uint4*>(Ab + d4 * 128 + 4);
            uint4 bl = *reinterpret_cast<const uint4*>(Bb + d4 * 128);
            uint4 bh = *reinterpret_cast<const uint4*>(Bb + d4 * 128 + 4);
            unsigned a[8] = {al.x, al.y, al.z, al.w, ah.x, ah.y, ah.z, ah.w};
            unsigned b[8] = {bl.x, bl.y, bl.z, bl.w, bh.x, bh.y, bh.z, bh.w};
#pragma unroll
            for (int i = 0; i < 8; i++)
#pragma unroll
                for (int j = 0; j < 8; j++)
                    acc[i][j] = __dp4a((int)a[i], (int)b[j], acc[i][j]);
        }

        // ---- pass 1: upper bounds -> running min; stash lower bounds ----
        const int c0 = ct * CTILE + tx * 8;
        float cs[8], s2[8], e1[8], n1[8];
#pragma unroll
        for (int j = 0; j < 8; j++) {
            cs[j] = __ldg(&g_csq[c0 + j]);
            s2[j] = __ldg(&g_sc2[c0 + j]);
            e1[j] = __ldg(&g_e1[c0 + j]);
            n1[j] = __ldg(&g_n1[c0 + j]);
        }
        float umin[8];
#pragma unroll
        for (int i = 0; i < 8; i++) {
            float um = 3.4e38f;
#pragma unroll
            for (int j = 0; j < 8; j++) {
                float f    = (float)acc[i][j] * s2[j];
                float dist = fmaf(-sxv[i], f, cs[j]);
                float bb   = fmaf(a0v[i], e1[j], a1v[i] * (n1[j] + e1[j]));
                float up   = fmaf(2.f, bb, dist) + 0.25f;
                float lo   = fmaf(-2.f, bb, dist) - 0.25f;
                um = fminf(um, up);
                acc[i][j] = (int)__float_as_uint(lo);   // stash lower bound
            }
            umin[i] = um;
        }
#pragma unroll
        for (int i = 0; i < 8; i++) {
            unsigned o = ford(umin[i]);
            if (o < minu[ty * 8 + i]) atomicMin(&minu[ty * 8 + i], o);
        }
        __syncthreads();

        // ---- pass 2: collect candidates ----
#pragma unroll
        for (int i = 0; i < 8; i++) {
            const int tok = ty * 8 + i;
            const float T = ford_inv(minu[tok]);
#pragma unroll
            for (int j = 0; j < 8; j++) {
                float lo = __uint_as_float((unsigned)acc[i][j]);
                if (lo <= T) {
                    int slot = atomicAdd(&cnts[tok], 1);
                    if (slot < CAP) g_cand[(size_t)(n0 + tok) * CAP + slot] = c0 + j;
                }
            }
        }
        __syncthreads();
    }

    if (tid < MTILE) g_cnt[n0 + tid] = cnts[tid];
}

// ---------------- exact rescore: 1 warp per token ----------------
__global__ __launch_bounds__(256) void rescore_kernel(const float* __restrict__ x,
                                                      const float* __restrict__ cb) {
    const int n = blockIdx.x * 8 + (threadIdx.x >> 5);
    const int lane = threadIdx.x & 31;

    const float* xr = x + ((size_t)(n >> 10) * DIM) * HW + (n & (HW - 1));
    float xv[8];
#pragma unroll
    for (int t = 0; t < 8; t++) xv[t] = xr[(size_t)(lane + 32 * t) * HW];

    const int cnt = g_cnt[n];
    const bool full = (cnt == 0 || cnt > CAP);
    const int m = full ? KCODES : cnt;

    float best = 3.4e38f;
    int bi = KCODES;
    for (int i = 0; i < m; i++) {
        const int c = full ? i : g_cand[(size_t)n * CAP + i];
        const float* cr = cb + (size_t)c * DIM;
        float dot = 0.f;
#pragma unroll
        for (int t = 0; t < 8; t++) dot = fmaf(xv[t], cr[lane + 32 * t], dot);
#pragma unroll
        for (int o = 16; o > 0; o >>= 1) dot += __shfl_xor_sync(0xFFFFFFFFu, dot, o);
        if (lane == 0) {
            const float dist = fmaf(-2.f, dot, g_csq[c]);
            if (dist < best || (dist == best && c < bi)) { best = dist; bi = c; }
        }
    }
    if (lane == 0) g_idx[n] = bi;
}

__global__ void gather_kernel(const float* __restrict__ cb, float* __restrict__ out) {
    int o = blockIdx.x * blockDim.x + threadIdx.x;
    int p = o & (HW - 1);
    int d = (o >> 10) & (DIM - 1);
    int b = o >> 18;
    int n = (b << 10) + p;
    out[o] = cb[(size_t)g_idx[n] * DIM + d];
}

extern "C" void kernel_launch(void* const* d_in, const int* in_sizes, int n_in,
                              void* d_out, int out_size) {
    const float* x  = (const float*)d_in[0];
    const float* cb = (const float*)d_in[1];
    float* out = (float*)d_out;

    cudaFuncSetAttribute(sweep_kernel, cudaFuncAttributeMaxDynamicSharedMemorySize, SM_TOT);

    quant_cb<<<KCODES / 8, 256>>>(cb);
    quant_x<<<NTOK / 128, 128>>>(x);
    sweep_kernel<<<NTOK / MTILE, 256, SM_TOT>>>();
    rescore_kernel<<<NTOK / 8, 256>>>(x, cb);
    gather_kernel<<<(NTOK * DIM) / 256, 256>>>(cb, out);
}

// round 5
// speedup vs baseline: 3.2167x; 3.2167x over previous
#include <cuda_runtime.h>
#include <stdint.h>

// ============================================================================
// Exact VQ argmin via packed fp32x2 FMA (SASS FFMA2, 2 MAC/instr, 2x fp32).
//   prep:  transpose codebook -> cbT[d][code];  csqh[c] = -0.5*||c||^2
//   sweep: per CTA 128 tokens (A resident in smem, full D=256);
//          loop 16 code-tiles x 16 d-chunks (cp.async double buffer);
//          acc(init=csqh) += x*c  via fma.rn.f32x2, 8tok x 16code / thread;
//          argmax(acc) == argmin distance. Exact fp32 -> no rescore needed.
//   gather: out = codebook[idx]
// ============================================================================

#define NTOK   16384
#define DIM    256
#define KCODES 4096
#define HW     1024
#define MTILE  128
#define CTILE  256              // codes per tile
#define NCT    (KCODES / CTILE) // 16
#define DC     16               // dims per chunk
#define NCH    (DIM / DC)       // 16
#define NCHUNK (NCT * NCH)      // 256

// smem (bytes)
#define SM_A    0                 // 256 d x 128 tok x 4B = 131072
#define SM_B    131072            // 2 x 16 d x 1024B     = 32768
#define SM_Q    163840            // csqh 4096 f32        = 16384
#define SM_BEST 180224            // 128 u64              = 1024
#define SM_TOT  181248

__device__ float g_cbT[DIM * KCODES];   // [d][code]
__device__ float g_csqh[KCODES];        // -0.5*||c||^2
__device__ int   g_idx[NTOK];

// ---------------- helpers ----------------
typedef unsigned long long u64;
__device__ __forceinline__ uint32_t smem_u32(const void* p) {
    uint32_t a;
    asm("{ .reg .u64 t; cvta.to.shared.u64 t, %1; cvt.u32.u64 %0, t; }" : "=r"(a) : "l"(p));
    return a;
}
__device__ __forceinline__ unsigned ford(float f) {    // order-preserving
    unsigned u = __float_as_uint(f);
    return (u & 0x80000000u) ? ~u : (u | 0x80000000u);
}
__device__ __forceinline__ u64 pack2(float v) {
    u64 r; unsigned b = __float_as_uint(v);
    asm("mov.b64 %0, {%1, %1};" : "=l"(r) : "r"(b));
    return r;
}
__device__ __forceinline__ void fma2(u64& acc, u64 a, u64 b) {
    asm("fma.rn.f32x2 %0, %1, %2, %0;" : "+l"(acc) : "l"(a), "l"(b));
}
__device__ __forceinline__ void lds_v2u64(u64& r0, u64& r1, uint32_t a) {
    asm volatile("ld.shared.v2.u64 {%0,%1}, [%2];" : "=l"(r0), "=l"(r1) : "r"(a));
}
#define CP16(d, s)  asm volatile("cp.async.cg.shared.global [%0], [%1], 16;" :: "r"(d), "l"(s))
#define CPCOMMIT()  asm volatile("cp.async.commit_group;" ::: "memory")
#define CPWAIT1()   asm volatile("cp.async.wait_group 1;" ::: "memory")
#define CPWAIT0()   asm volatile("cp.async.wait_group 0;" ::: "memory")

// ---------------- prep: transpose codebook ----------------
__global__ __launch_bounds__(256) void tr_kernel(const float* __restrict__ cb) {
    __shared__ float t[32][33];
    const int c0 = blockIdx.x * 32;                  // code block
    const int d0 = blockIdx.y * 32;                  // dim block
    const int tx = threadIdx.x & 31, ty8 = threadIdx.x >> 5;   // 8 rows/pass
#pragma unroll
    for (int r = 0; r < 4; r++)
        t[ty8 + r * 8][tx] = cb[(size_t)(c0 + ty8 + r * 8) * DIM + d0 + tx];
    __syncthreads();
#pragma unroll
    for (int r = 0; r < 4; r++)
        g_cbT[(size_t)(d0 + ty8 + r * 8) * KCODES + c0 + tx] = t[tx][ty8 + r * 8];
}

// ---------------- prep: -0.5*||c||^2 (one warp / code) ----------------
__global__ __launch_bounds__(256) void csqh_kernel(const float* __restrict__ cb) {
    const int code = blockIdx.x * 8 + (threadIdx.x >> 5);
    const int lane = threadIdx.x & 31;
    const float* row = cb + (size_t)code * DIM;
    float s = 0.f;
#pragma unroll
    for (int i = 0; i < 8; i++) {
        float v = row[lane + 32 * i];
        s = fmaf(v, v, s);
    }
#pragma unroll
    for (int o = 16; o > 0; o >>= 1) s += __shfl_xor_sync(0xFFFFFFFFu, s, o);
    if (lane == 0) g_csqh[code] = -0.5f * s;
}

// ---------------- main sweep ----------------
__global__ __launch_bounds__(256, 1) void sweep_kernel(const float* __restrict__ x) {
    extern __shared__ char sm[];
    float* A      = reinterpret_cast<float*>(sm + SM_A);     // [d][tok], stride 128
    float* csqh_s = reinterpret_cast<float*>(sm + SM_Q);
    u64*   sbest  = reinterpret_cast<u64*>(sm + SM_BEST);
    const uint32_t sb = smem_u32(sm);

    const int tid = threadIdx.x;
    const int tx  = tid & 15;       // code group
    const int ty  = tid >> 4;       // token group (8 tokens)
    const int n0  = blockIdx.x * MTILE;
    const char* xb = reinterpret_cast<const char*>(
        x + (size_t)(n0 >> 10) * DIM * HW + (n0 & (HW - 1)));

    // A fill (group 0): 256 rows of 512B, coalesced
    for (int s = tid; s < 8192; s += 256) {
        int d = s >> 5, seg = s & 31;
        CP16(sb + SM_A + d * 512 + seg * 16, xb + (size_t)d * 4096 + seg * 16);
    }
    CPCOMMIT();
    // csqh + best init
    for (int i = tid; i < KCODES; i += 256) csqh_s[i] = g_csqh[i];
    if (tid < MTILE) sbest[tid] = 0ull;
    // B chunk 0 (group 1)
    {
        const char* src = reinterpret_cast<const char*>(g_cbT);
        for (int s = tid; s < 1024; s += 256) {
            int r = s >> 6, seg = s & 63;
            CP16(sb + SM_B + r * 1024 + seg * 16, src + (size_t)r * (KCODES * 4) + seg * 16);
        }
        CPCOMMIT();
    }

    float bestv[8];
    int   bestc[8];
#pragma unroll
    for (int i = 0; i < 8; i++) { bestv[i] = -3.4e38f; bestc[i] = 0; }

    u64 acc[8][8];

    for (int cidx = 0; cidx < NCHUNK; cidx++) {
        const int ct = cidx >> 4;
        const int dc = cidx & 15;
        const int p  = cidx & 1;

        // prefetch next chunk
        if (cidx + 1 < NCHUNK) {
            const int nct = (cidx + 1) >> 4, ndc = (cidx + 1) & 15;
            const char* src = reinterpret_cast<const char*>(
                g_cbT + (size_t)(ndc * DC) * KCODES + nct * CTILE);
            const uint32_t dst = sb + SM_B + ((cidx + 1) & 1) * 16384;
            for (int s = tid; s < 1024; s += 256) {
                int r = s >> 6, seg = s & 63;
                CP16(dst + r * 1024 + seg * 16, src + (size_t)r * (KCODES * 4) + seg * 16);
            }
            CPCOMMIT();
            CPWAIT1();
        } else {
            CPWAIT0();
        }
        __syncthreads();

        // acc init at tile start: -0.5*||c||^2 pairs
        if (dc == 0) {
            const int qb = ct * CTILE + tx * 4;
#pragma unroll
            for (int s = 0; s < 4; s++) {
                u64 k0 = *reinterpret_cast<const u64*>(csqh_s + qb + s * 64);
                u64 k1 = *reinterpret_cast<const u64*>(csqh_s + qb + s * 64 + 2);
#pragma unroll
                for (int i = 0; i < 8; i++) { acc[i][s * 2] = k0; acc[i][s * 2 + 1] = k1; }
            }
        }

        // ---- compute 16 d-steps ----
        const float*   Abase = A + dc * DC * 128 + ty * 8;
        const uint32_t Bbase = sb + SM_B + p * 16384 + tx * 16;
#pragma unroll 4
        for (int k = 0; k < DC; k++) {
            const float4 a0 = *reinterpret_cast<const float4*>(Abase + k * 128);
            const float4 a1 = *reinterpret_cast<const float4*>(Abase + k * 128 + 4);
            u64 pa[8];
            pa[0] = pack2(a0.x); pa[1] = pack2(a0.y);
            pa[2] = pack2(a0.z); pa[3] = pack2(a0.w);
            pa[4] = pack2(a1.x); pa[5] = pack2(a1.y);
            pa[6] = pack2(a1.z); pa[7] = pack2(a1.w);
            u64 bb[8];
#pragma unroll
            for (int s = 0; s < 4; s++)
                lds_v2u64(bb[s * 2], bb[s * 2 + 1], Bbase + k * 1024 + s * 256);
#pragma unroll
            for (int i = 0; i < 8; i++)
#pragma unroll
                for (int j = 0; j < 8; j++)
                    fma2(acc[i][j], pa[i], bb[j]);
        }
        __syncthreads();   // buffer consumed; next iter may overwrite

        // ---- tile epilogue: running argmax ----
        if (dc == 15) {
            const int cb0 = ct * CTILE + tx * 4;
#pragma unroll
            for (int i = 0; i < 8; i++)
#pragma unroll
                for (int s = 0; s < 4; s++)
#pragma unroll
                    for (int q = 0; q < 2; q++) {
                        unsigned lo, hi;
                        asm("mov.b64 {%0,%1}, %2;" : "=r"(lo), "=r"(hi) : "l"(acc[i][s * 2 + q]));
                        float v0 = __uint_as_float(lo), v1 = __uint_as_float(hi);
                        int c = cb0 + s * 64 + q * 2;
                        if (v0 > bestv[i]) { bestv[i] = v0; bestc[i] = c; }
                        if (v1 > bestv[i]) { bestv[i] = v1; bestc[i] = c + 1; }
                    }
        }
    }

    // ---- cross-thread reduction: max value, then min code ----
#pragma unroll
    for (int i = 0; i < 8; i++) {
        u64 key = ((u64)ford(bestv[i]) << 32) | (u64)(0xFFFFFFFFu - (unsigned)bestc[i]);
        atomicMax(&sbest[ty * 8 + i], key);
    }
    __syncthreads();
    if (tid < MTILE) {
        unsigned low = (unsigned)(sbest[tid] & 0xFFFFFFFFull);
        g_idx[n0 + tid] = (int)(0xFFFFFFFFu - low);
    }
}

// ---------------- gather ----------------
__global__ void gather_kernel(const float* __restrict__ cb, float* __restrict__ out) {
    int o = blockIdx.x * blockDim.x + threadIdx.x;
    int p = o & (HW - 1);
    int d = (o >> 10) & (DIM - 1);
    int b = o >> 18;
    int n = (b << 10) + p;
    out[o] = cb[(size_t)g_idx[n] * DIM + d];
}

extern "C" void kernel_launch(void* const* d_in, const int* in_sizes, int n_in,
                              void* d_out, int out_size) {
    const float* x  = (const float*)d_in[0];
    const float* cb = (const float*)d_in[1];
    float* out = (float*)d_out;

    cudaFuncSetAttribute(sweep_kernel, cudaFuncAttributeMaxDynamicSharedMemorySize, SM_TOT);

    tr_kernel<<<dim3(KCODES / 32, DIM / 32), 256>>>(cb);
    csqh_kernel<<<KCODES / 8, 256>>>(cb);
    sweep_kernel<<<NTOK / MTILE, 256, SM_TOT>>>(x);
    gather_kernel<<<(NTOK * DIM) / 256, 256>>>(cb, out);
}